// round 14
// baseline (speedup 1.0000x reference)
#include <cuda_runtime.h>
#include <cuda_fp16.h>
#include <cstdint>
#include <math.h>

// ============================================================================
// ChessNNUE kernels (sm_103-compatible: mma.sync fp16 + ldmatrix + cp.async)
//   prep: fp32 -> fp16 for ft_w, l1_w
//   main: TILEM=64, 512 thr, 16 warps = 4M x 2N x 2K-split (4 warps/SMSP)
//         warp tile 16M x 32N x k32 (w+b). resident-A, 3-buffer k64 ft pipe,
//         race-fixed pipeline. K-merge at pass ends via freed ft ring buffer.
//   head: l1 sums -> l2 -> l3 -> sigmoid (separate tiny kernel)
// ============================================================================

static constexpr int KDIM = 768;
static constexpr int HID  = 1024;
static constexpr int TILEM = 64;
static constexpr int NTHREADS = 512;
static constexpr int KT_PER_PASS = 12;                 // 768 / 64 (k64 tiles)
static constexpr int NPASS = 16;                       // 1024 / 64
static constexpr int NTILES = NPASS * KT_PER_PASS;     // 192
static constexpr int MAXB = 65536;

__device__ __align__(128) __half g_ftw_h[(size_t)HID * KDIM];
__device__ __align__(128) __half g_l1wh[8 * 2 * HID];
__device__ __align__(128) float  g_l1out[(size_t)MAXB * 8];

// ---- smem layout ----
static constexpr uint32_t A_STRIDE_B = 776 * 2;               // 1552 B/row (97x16B)
static constexpr uint32_t A_BYTES    = TILEM * A_STRIDE_B;    // 99328
static constexpr uint32_t OFF_AW     = 0;
static constexpr uint32_t OFF_AB     = A_BYTES;               // 99328
static constexpr uint32_t FT_STRIDE  = 144;                   // 128B data + 16B pad
static constexpr uint32_t FT_TILE    = 64 * FT_STRIDE;        // 9216 (64 n, k64)
static constexpr uint32_t OFF_FT     = 2 * A_BYTES;           // 198656 (3 buffers)
static constexpr uint32_t SMEM_DYN   = OFF_FT + 3 * FT_TILE;  // 226304
// K-merge scratch + final sred alias freed ft ring buffers.

// ---------------------------------------------------------------------------
__device__ __forceinline__ uint32_t smem_u32(const void* p) {
    uint32_t a;
    asm("{ .reg .u64 t; cvta.to.shared.u64 t, %1; cvt.u32.u64 %0, t; }" : "=r"(a) : "l"(p));
    return a;
}
__device__ __forceinline__ void cp16(uint32_t dst, const void* src) {
    asm volatile("cp.async.cg.shared.global [%0], [%1], 16;" :: "r"(dst), "l"(src));
}
#define CP_COMMIT()  asm volatile("cp.async.commit_group;" ::: "memory")
#define CP_WAIT(n)   asm volatile("cp.async.wait_group %0;" :: "n"(n) : "memory")

__device__ __forceinline__ void ldsm4(uint32_t& r0, uint32_t& r1, uint32_t& r2,
                                      uint32_t& r3, uint32_t addr) {
    asm volatile("ldmatrix.sync.aligned.m8n8.x4.shared.b16 {%0,%1,%2,%3}, [%4];"
                 : "=r"(r0), "=r"(r1), "=r"(r2), "=r"(r3) : "r"(addr));
}
__device__ __forceinline__ void mma_f16(float c[4], uint32_t a0, uint32_t a1,
                                        uint32_t a2, uint32_t a3,
                                        uint32_t b0, uint32_t b1) {
    asm volatile(
        "mma.sync.aligned.m16n8k16.row.col.f32.f16.f16.f32 "
        "{%0,%1,%2,%3}, {%4,%5,%6,%7}, {%8,%9}, {%0,%1,%2,%3};\n"
        : "+f"(c[0]), "+f"(c[1]), "+f"(c[2]), "+f"(c[3])
        : "r"(a0), "r"(a1), "r"(a2), "r"(a3), "r"(b0), "r"(b1));
}
__device__ __forceinline__ float clip01(float x) {
    return fminf(fmaxf(x, 0.0f), 1.0f);
}
__device__ __forceinline__ uint32_t pack_h2(float lo, float hi) {
    __half2 v = __floats2half2_rn(lo, hi);
    return *reinterpret_cast<uint32_t*>(&v);
}

// ---------------------------------------------------------------------------
// prep: fp32 -> fp16 for ft_w and l1_w
// ---------------------------------------------------------------------------
__global__ void nnue_prep(const float* __restrict__ fw, const float* __restrict__ l1w) {
    int i0 = blockIdx.x * blockDim.x + threadIdx.x;
    int stride = gridDim.x * blockDim.x;
    __half2* fdst = reinterpret_cast<__half2*>(g_ftw_h);
    __half2* ldst = reinterpret_cast<__half2*>(g_l1wh);
    const float2* fsrc = reinterpret_cast<const float2*>(fw);
    const float2* lsrc = reinterpret_cast<const float2*>(l1w);
    for (int j = i0; j < HID * KDIM / 2; j += stride) {
        float2 a = fsrc[j]; fdst[j] = __floats2half2_rn(a.x, a.y);
    }
    for (int j = i0; j < 8 * 2 * HID / 2; j += stride) {
        float2 a = lsrc[j]; ldst[j] = __floats2half2_rn(a.x, a.y);
    }
}

// ---------------------------------------------------------------------------
// main: feature transform + mix + clip + l1 partials
// ---------------------------------------------------------------------------
__global__ __launch_bounds__(NTHREADS, 1) void nnue_main(
    const float* __restrict__ white, const float* __restrict__ black,
    const float* __restrict__ stm, const float* __restrict__ ftb) {
    extern __shared__ char smc[];
    const uint32_t sb = smem_u32(smc);

    const int tid = threadIdx.x;
    const int lane = tid & 31;
    const int wid = tid >> 5;
    const int warpK = wid & 1;          // k-half of each k64 tile
    const int warpN = (wid >> 1) & 1;   // cols warpN*32 .. +31 within 64-pass
    const int warpM = wid >> 2;         // rows warpM*16 .. +15 (0..3)
    const int row0 = blockIdx.x * TILEM;

    // ---- prefetch ft k64-tiles 0,1 (pass 0): 512 chunks/tile, 1/thread ----
    {
        int r = tid >> 3, c = tid & 7;
        cp16(sb + OFF_FT + r * FT_STRIDE + c * 16, g_ftw_h + (size_t)r * KDIM + c * 8);
        CP_COMMIT();   // group: tile 0
        cp16(sb + OFF_FT + FT_TILE + r * FT_STRIDE + c * 16,
             g_ftw_h + (size_t)r * KDIM + 64 + c * 8);
        CP_COMMIT();   // group: tile 1
    }

    // ---- stage resident A: fp32 LDG -> fp16 STS (w and b, 64x768 each) ----
    {
        const int r = tid >> 3, cb = tid & 7;           // r: 0..63
        const float* wsrc = white + (size_t)(row0 + r) * KDIM;
        const float* bsrc = black + (size_t)(row0 + r) * KDIM;
        char* wdst = smc + OFF_AW + r * A_STRIDE_B;
        char* bdst = smc + OFF_AB + r * A_STRIDE_B;
#pragma unroll
        for (int it = 0; it < 12; it++) {
            const int c = cb + it * 8;   // 16B fp16 group index (0..95)
            float4 x = *reinterpret_cast<const float4*>(wsrc + c * 8);
            float4 y = *reinterpret_cast<const float4*>(wsrc + c * 8 + 4);
            uint4 v;
            v.x = pack_h2(x.x, x.y); v.y = pack_h2(x.z, x.w);
            v.z = pack_h2(y.x, y.y); v.w = pack_h2(y.z, y.w);
            *reinterpret_cast<uint4*>(wdst + c * 16) = v;
            float4 p = *reinterpret_cast<const float4*>(bsrc + c * 8);
            float4 q = *reinterpret_cast<const float4*>(bsrc + c * 8 + 4);
            uint4 u;
            u.x = pack_h2(p.x, p.y); u.y = pack_h2(p.z, p.w);
            u.z = pack_h2(q.x, q.y); u.w = pack_h2(q.z, q.w);
            *reinterpret_cast<uint4*>(bdst + c * 16) = u;
        }
    }

    const float stm_lo = stm[row0 + warpM * 16 + (lane >> 2)];
    const float stm_hi = stm[row0 + warpM * 16 + (lane >> 2) + 8];

    // ---- ldmatrix lane addresses (R6-validated mappings + warpK k-offset) ----
    const uint32_t awA = sb + OFF_AW + (warpM * 16 + (lane & 15)) * A_STRIDE_B +
                         (lane >> 4) * 16 + (uint32_t)warpK * 64;
    const uint32_t abA = awA + (OFF_AB - OFF_AW);
    const uint32_t btA0 = (uint32_t)(warpN * 32 + ((lane >> 4) << 3) + (lane & 7)) *
                              FT_STRIDE + ((lane >> 3) & 1) * 16 + (uint32_t)warpK * 64;
    const uint32_t btA1 = btA0 + 16 * FT_STRIDE;

    float wacc[4][4] = {}, bacc[4][4] = {}, sacc[4] = {};

    for (int t = 0; t < NTILES; t++) {
        CP_WAIT(1);        // tile t's copies retired (only t+1 pending)
        __syncthreads();   // tile-t visible CTA-wide; all lanes done with t-1

        if (t + 2 < NTILES) {   // prefetch tile t+2 into buffer freed by t-1
            const int nt = t + 2;
            const int n0 = (nt / KT_PER_PASS) * 64, k0n = (nt % KT_PER_PASS) * 64;
            const uint32_t db = sb + OFF_FT + (uint32_t)(nt % 3) * FT_TILE;
            int r = tid >> 3, c = tid & 7;
            cp16(db + r * FT_STRIDE + c * 16,
                 g_ftw_h + (size_t)(n0 + r) * KDIM + k0n + c * 8);
        }
        CP_COMMIT();       // exactly one group per iteration

        const uint32_t bt = sb + OFF_FT + (uint32_t)(t % 3) * FT_TILE;
        const uint32_t ak = (uint32_t)((t % KT_PER_PASS) * 128);  // k64 = 128B

#pragma unroll
        for (int ks = 0; ks < 2; ks++) {   // this warp's k32 half, two k16 steps
            uint32_t aw[4], ab[4], b0f[4], b1f[4];
            ldsm4(aw[0], aw[1], aw[2], aw[3], awA + ak + ks * 32);
            ldsm4(ab[0], ab[1], ab[2], ab[3], abA + ak + ks * 32);
            ldsm4(b0f[0], b0f[1], b0f[2], b0f[3], bt + btA0 + ks * 32);
            ldsm4(b1f[0], b1f[1], b1f[2], b1f[3], bt + btA1 + ks * 32);
            mma_f16(wacc[0], aw[0], aw[1], aw[2], aw[3], b0f[0], b0f[1]);
            mma_f16(wacc[1], aw[0], aw[1], aw[2], aw[3], b0f[2], b0f[3]);
            mma_f16(wacc[2], aw[0], aw[1], aw[2], aw[3], b1f[0], b1f[1]);
            mma_f16(wacc[3], aw[0], aw[1], aw[2], aw[3], b1f[2], b1f[3]);
            mma_f16(bacc[0], ab[0], ab[1], ab[2], ab[3], b0f[0], b0f[1]);
            mma_f16(bacc[1], ab[0], ab[1], ab[2], ab[3], b0f[2], b0f[3]);
            mma_f16(bacc[2], ab[0], ab[1], ab[2], ab[3], b1f[0], b1f[1]);
            mma_f16(bacc[3], ab[0], ab[1], ab[2], ab[3], b1f[2], b1f[3]);
        }

        // ---- pass end: K-merge, then +ftb, stm mix, clip, l1 via mma ----
        if ((t % KT_PER_PASS) == KT_PER_PASS - 1) {
            const int pass = t / KT_PER_PASS;
            // merge K1 partials into K0 via the JUST-FREED ft buffer (t%3):
            // next write into it (prefetch t+3) is ordered after the t+1 barrier.
            float* scratch = reinterpret_cast<float*>(smc + OFF_FT +
                                                      (uint32_t)(t % 3) * FT_TILE);
            const int pair = warpM * 2 + warpN;   // 0..7; waves of 2 pairs (8KB)
#pragma unroll 1
            for (int wv = 0; wv < 4; wv++) {
                __syncthreads();
                if ((pair >> 1) == wv && warpK == 1) {
                    float* s = scratch + (pair & 1) * 1024 + lane * 32;
#pragma unroll
                    for (int f = 0; f < 4; f++) {
#pragma unroll
                        for (int j = 0; j < 4; j++) {
                            s[f * 4 + j] = wacc[f][j];
                            s[16 + f * 4 + j] = bacc[f][j];
                        }
                    }
                }
                __syncthreads();
                if ((pair >> 1) == wv && warpK == 0) {
                    const float* s = scratch + (pair & 1) * 1024 + lane * 32;
#pragma unroll
                    for (int f = 0; f < 4; f++) {
#pragma unroll
                        for (int j = 0; j < 4; j++) {
                            wacc[f][j] += s[f * 4 + j];
                            bacc[f][j] += s[16 + f * 4 + j];
                        }
                    }
                }
            }

            if (warpK == 0) {   // epilogue (R6-validated), zeroes accs inside
#pragma unroll
                for (int kg = 0; kg < 2; kg++) {
                    uint32_t A1[4], A2[4];
#pragma unroll
                    for (int h = 0; h < 2; h++) {
                        const int f = kg * 2 + h;
                        const int nidx = pass * 64 + warpN * 32 + f * 8 + 2 * (lane & 3);
                        const float2 fb = __ldg(reinterpret_cast<const float2*>(ftb + nidx));
                        float a1v[4], a2v[4];
#pragma unroll
                        for (int j = 0; j < 4; j++) {
                            const float fbv = (j & 1) ? fb.y : fb.x;
                            const float sv = (j < 2) ? stm_lo : stm_hi;
                            const float wv = wacc[f][j] + fbv;
                            const float bv = bacc[f][j] + fbv;
                            a1v[j] = clip01(sv * wv + (1.0f - sv) * bv);
                            a2v[j] = clip01(sv * bv + (1.0f - sv) * wv);
                        }
                        A1[h * 2 + 0] = pack_h2(a1v[0], a1v[1]);
                        A1[h * 2 + 1] = pack_h2(a1v[2], a1v[3]);
                        A2[h * 2 + 0] = pack_h2(a2v[0], a2v[1]);
                        A2[h * 2 + 1] = pack_h2(a2v[2], a2v[3]);
                        wacc[f][0] = wacc[f][1] = wacc[f][2] = wacc[f][3] = 0.0f;
                        bacc[f][0] = bacc[f][1] = bacc[f][2] = bacc[f][3] = 0.0f;
                    }
                    const int kcol = pass * 64 + warpN * 32 + kg * 16 + 2 * (lane & 3);
                    const __half* bp = g_l1wh + (size_t)(lane >> 2) * (2 * HID) + kcol;
                    uint32_t B10 = *reinterpret_cast<const uint32_t*>(bp);
                    uint32_t B11 = *reinterpret_cast<const uint32_t*>(bp + 8);
                    uint32_t B20 = *reinterpret_cast<const uint32_t*>(bp + HID);
                    uint32_t B21 = *reinterpret_cast<const uint32_t*>(bp + HID + 8);
                    mma_f16(sacc, A1[0], A1[1], A1[2], A1[3], B10, B11);
                    mma_f16(sacc, A2[0], A2[1], A2[2], A2[3], B20, B21);
                }
            } else {            // K1: reset partial accumulators
#pragma unroll
                for (int f = 0; f < 4; f++) {
                    wacc[f][0] = wacc[f][1] = wacc[f][2] = wacc[f][3] = 0.0f;
                    bacc[f][0] = bacc[f][1] = bacc[f][2] = bacc[f][3] = 0.0f;
                }
            }
        }
    }

    // ---- reduce l1 partials across 2 warpN groups, write to global ----
    __syncthreads();
    float* sred = reinterpret_cast<float*>(smc + OFF_FT);  // 2 x 64 x 8 floats
    if (warpK == 0) {
        const int rlo = warpM * 16 + (lane >> 2);
        const int o0 = 2 * (lane & 3);
        float* g = sred + warpN * (TILEM * 8);
        g[rlo * 8 + o0] = sacc[0];
        g[rlo * 8 + o0 + 1] = sacc[1];
        g[(rlo + 8) * 8 + o0] = sacc[2];
        g[(rlo + 8) * 8 + o0 + 1] = sacc[3];
    }
    __syncthreads();

    if (tid < TILEM * 2) {   // 128 threads: (row, half) pairs write 4 floats each
        const int r = tid >> 1, half = tid & 1;
        float4 a = *reinterpret_cast<const float4*>(sred + r * 8 + half * 4);
        float4 b = *reinterpret_cast<const float4*>(sred + TILEM * 8 + r * 8 + half * 4);
        float4 s;
        s.x = a.x + b.x; s.y = a.y + b.y; s.z = a.z + b.z; s.w = a.w + b.w;
        *reinterpret_cast<float4*>(g_l1out + (size_t)(row0 + r) * 8 + half * 4) = s;
    }
}

// ---------------------------------------------------------------------------
// head: l1 sums -> l2 -> l3 -> sigmoid
// ---------------------------------------------------------------------------
__global__ __launch_bounds__(256) void nnue_head(
    const float* __restrict__ l1b, const float* __restrict__ l2w,
    const float* __restrict__ l2b, const float* __restrict__ l3w,
    const float* __restrict__ l3b, float* __restrict__ out, int B) {
    const int gr = blockIdx.x * 256 + threadIdx.x;
    const float4 s0 = *reinterpret_cast<const float4*>(g_l1out + (size_t)gr * 8);
    const float4 s1 = *reinterpret_cast<const float4*>(g_l1out + (size_t)gr * 8 + 4);
    float l2x[8];
    l2x[0] = clip01(s0.x + __ldg(&l1b[0]));
    l2x[1] = clip01(s0.y + __ldg(&l1b[1]));
    l2x[2] = clip01(s0.z + __ldg(&l1b[2]));
    l2x[3] = clip01(s0.w + __ldg(&l1b[3]));
    l2x[4] = clip01(s1.x + __ldg(&l1b[4]));
    l2x[5] = clip01(s1.y + __ldg(&l1b[5]));
    l2x[6] = clip01(s1.z + __ldg(&l1b[6]));
    l2x[7] = clip01(s1.w + __ldg(&l1b[7]));
    float rawv = __ldg(&l3b[0]);
#pragma unroll 1
    for (int j = 0; j < 32; j++) {
        float tacc = __ldg(&l2b[j]);
#pragma unroll
        for (int o = 0; o < 8; o++) tacc += __ldg(&l2w[j * 8 + o]) * l2x[o];
        rawv += __ldg(&l3w[j]) * clip01(tacc);
    }
    out[gr] = 1.0f / (1.0f + expf(-rawv));
    out[B + gr] = rawv;
}

// ---------------------------------------------------------------------------
// launch
// ---------------------------------------------------------------------------
extern "C" void kernel_launch(void* const* d_in, const int* in_sizes, int n_in,
                              void* d_out, int out_size) {
    const float* white = (const float*)d_in[0];
    const float* black = (const float*)d_in[1];
    const float* stm   = (const float*)d_in[2];
    const float* ftw   = (const float*)d_in[3];
    const float* ftb   = (const float*)d_in[4];
    const float* l1w   = (const float*)d_in[5];
    const float* l1b   = (const float*)d_in[6];
    const float* l2w   = (const float*)d_in[7];
    const float* l2b   = (const float*)d_in[8];
    const float* l3w   = (const float*)d_in[9];
    const float* l3b   = (const float*)d_in[10];
    float* out = (float*)d_out;

    const int B = in_sizes[2];

    nnue_prep<<<512, 256>>>(ftw, l1w);

    static int configured = 0;
    if (!configured) {
        cudaFuncSetAttribute(nnue_main, cudaFuncAttributeMaxDynamicSharedMemorySize,
                             SMEM_DYN);
        configured = 1;
    }
    nnue_main<<<B / TILEM, NTHREADS, SMEM_DYN>>>(white, black, stm, ftb);
    nnue_head<<<B / 256, 256>>>(l1b, l2w, l2b, l3w, l3b, out, B);
}

// round 15
// speedup vs baseline: 1.4099x; 1.4099x over previous
#include <cuda_runtime.h>
#include <cuda_fp16.h>
#include <cstdint>
#include <math.h>

// ============================================================================
// ChessNNUE kernels (sm_103-compatible: mma.sync fp16 + cp.async)
//   prep: fp32 -> fp16 for ft_w, l1_w only (6us)
//   main: R3-class mainloop (best measured): TILEM=64, 256 thr, 8 warps
//         (4M x 2N, warp tile 16M x 32N, w+b), resident-A converted in-kernel,
//         k96 ft tiles double-buffered (128 tiles, 2 syncs/tile),
//         scalar-LDS fragments, pass-end epilogue -> l1 partials -> g_l1out
//   head: l1 sums -> l2 -> l3 -> sigmoid (separate tiny kernel)
// ============================================================================

static constexpr int KDIM = 768;
static constexpr int HID  = 1024;
static constexpr int TILEM = 64;
static constexpr int NTHREADS = 256;
static constexpr int KT_PER_PASS = 8;                  // 768 / 96 (k96 tiles)
static constexpr int NPASS = 16;                       // 1024 / 64
static constexpr int NTILES = NPASS * KT_PER_PASS;     // 128
static constexpr int MAXB = 65536;

__device__ __align__(128) __half g_ftw_h[(size_t)HID * KDIM];
__device__ __align__(128) __half g_l1wh[8 * 2 * HID];
__device__ __align__(128) float  g_l1out[(size_t)MAXB * 8];

// ---- smem layout ----
static constexpr uint32_t A_STRIDE_B = 776 * 2;               // 1552 B/row (97x16B)
static constexpr uint32_t A_BYTES    = TILEM * A_STRIDE_B;    // 99328
static constexpr uint32_t OFF_AW     = 0;
static constexpr uint32_t OFF_AB     = A_BYTES;               // 99328
static constexpr uint32_t FT_STRIDE  = 208;                   // 192B data + 16B pad
static constexpr uint32_t FT_TILE    = 64 * FT_STRIDE;        // 13312 (64 n, k96)
static constexpr uint32_t OFF_FT     = 2 * A_BYTES;           // 198656 (2 buffers)
static constexpr uint32_t SMEM_DYN   = OFF_FT + 2 * FT_TILE;  // 225280 (<=232448)
// sred (2 x 64 x 8 fp32 = 4KB) aliases OFF_FT after the mainloop drains.

// ---------------------------------------------------------------------------
__device__ __forceinline__ uint32_t smem_u32(const void* p) {
    uint32_t a;
    asm("{ .reg .u64 t; cvta.to.shared.u64 t, %1; cvt.u32.u64 %0, t; }" : "=r"(a) : "l"(p));
    return a;
}
__device__ __forceinline__ void cp16(uint32_t dst, const void* src) {
    asm volatile("cp.async.cg.shared.global [%0], [%1], 16;" :: "r"(dst), "l"(src));
}
#define CP_COMMIT()  asm volatile("cp.async.commit_group;" ::: "memory")
#define CP_WAIT(n)   asm volatile("cp.async.wait_group %0;" :: "n"(n) : "memory")

__device__ __forceinline__ void mma_f16(float c[4], uint32_t a0, uint32_t a1,
                                        uint32_t a2, uint32_t a3,
                                        uint32_t b0, uint32_t b1) {
    asm volatile(
        "mma.sync.aligned.m16n8k16.row.col.f32.f16.f16.f32 "
        "{%0,%1,%2,%3}, {%4,%5,%6,%7}, {%8,%9}, {%0,%1,%2,%3};\n"
        : "+f"(c[0]), "+f"(c[1]), "+f"(c[2]), "+f"(c[3])
        : "r"(a0), "r"(a1), "r"(a2), "r"(a3), "r"(b0), "r"(b1));
}
__device__ __forceinline__ float clip01(float x) {
    return fminf(fmaxf(x, 0.0f), 1.0f);
}
__device__ __forceinline__ uint32_t pack_h2(float lo, float hi) {
    __half2 v = __floats2half2_rn(lo, hi);
    return *reinterpret_cast<uint32_t*>(&v);
}

// ---------------------------------------------------------------------------
// prep: fp32 -> fp16 for ft_w and l1_w
// ---------------------------------------------------------------------------
__global__ void nnue_prep(const float* __restrict__ fw, const float* __restrict__ l1w) {
    int i0 = blockIdx.x * blockDim.x + threadIdx.x;
    int stride = gridDim.x * blockDim.x;
    __half2* fdst = reinterpret_cast<__half2*>(g_ftw_h);
    __half2* ldst = reinterpret_cast<__half2*>(g_l1wh);
    const float2* fsrc = reinterpret_cast<const float2*>(fw);
    const float2* lsrc = reinterpret_cast<const float2*>(l1w);
    for (int j = i0; j < HID * KDIM / 2; j += stride) {
        float2 a = fsrc[j]; fdst[j] = __floats2half2_rn(a.x, a.y);
    }
    for (int j = i0; j < 8 * 2 * HID / 2; j += stride) {
        float2 a = lsrc[j]; ldst[j] = __floats2half2_rn(a.x, a.y);
    }
}

// ---------------------------------------------------------------------------
// main: feature transform + mix + clip + l1 partials
// ---------------------------------------------------------------------------
__global__ __launch_bounds__(NTHREADS, 1) void nnue_main(
    const float* __restrict__ white, const float* __restrict__ black,
    const float* __restrict__ stm, const float* __restrict__ ftb) {
    extern __shared__ char smc[];
    const uint32_t sb = smem_u32(smc);

    const int tid = threadIdx.x;
    const int lane = tid & 31;
    const int wid = tid >> 5;
    const int warpM = wid & 3;      // rows warpM*16 .. +15
    const int warpN = wid >> 2;     // cols warpN*32 .. +31 within 64-pass
    const int row0 = blockIdx.x * TILEM;

    // ---- prefetch ft tile 0 (pass 0, k0=0): 768 groups, 3/thread ----
    {
        const int r = tid >> 2, cb = tid & 3;     // 4 threads/row, 12 groups/row
#pragma unroll
        for (int j = 0; j < 3; j++) {
            const int c = cb + j * 4;
            cp16(sb + OFF_FT + r * FT_STRIDE + c * 16,
                 g_ftw_h + (size_t)r * KDIM + c * 8);
        }
        CP_COMMIT();   // group: tile 0
    }

    // ---- stage resident A: fp32 LDG -> fp16 STS (w and b, 64x768 each) ----
    {
        const int r = tid >> 2, cb = tid & 3;
        const float* wsrc = white + (size_t)(row0 + r) * KDIM;
        const float* bsrc = black + (size_t)(row0 + r) * KDIM;
        char* wdst = smc + OFF_AW + r * A_STRIDE_B;
        char* bdst = smc + OFF_AB + r * A_STRIDE_B;
#pragma unroll
        for (int it = 0; it < 24; it++) {
            const int c = cb + it * 4;   // 16B fp16 group index (0..95)
            float4 x = *reinterpret_cast<const float4*>(wsrc + c * 8);
            float4 y = *reinterpret_cast<const float4*>(wsrc + c * 8 + 4);
            uint4 v;
            v.x = pack_h2(x.x, x.y); v.y = pack_h2(x.z, x.w);
            v.z = pack_h2(y.x, y.y); v.w = pack_h2(y.z, y.w);
            *reinterpret_cast<uint4*>(wdst + c * 16) = v;
            float4 p = *reinterpret_cast<const float4*>(bsrc + c * 8);
            float4 q = *reinterpret_cast<const float4*>(bsrc + c * 8 + 4);
            uint4 u;
            u.x = pack_h2(p.x, p.y); u.y = pack_h2(p.z, p.w);
            u.z = pack_h2(q.x, q.y); u.w = pack_h2(q.z, q.w);
            *reinterpret_cast<uint4*>(bdst + c * 16) = u;
        }
    }

    const float stm_lo = stm[row0 + warpM * 16 + (lane >> 2)];
    const float stm_hi = stm[row0 + warpM * 16 + (lane >> 2) + 8];

    // scalar-LDS fragment base (best-measured mapping, R3-bench)
    const uint32_t a_row = sb + (warpM * 16 + (lane >> 2)) * A_STRIDE_B + (lane & 3) * 4;

    float wacc[4][4] = {}, bacc[4][4] = {}, sacc[4] = {};

    for (int t = 0; t < NTILES; t++) {
        // prefetch tile t+1 into buffer (t+1)&1 (freed at end of iter t-1)
        if (t + 1 < NTILES) {
            const int nt = t + 1;
            const int n0 = (nt / KT_PER_PASS) * 64, k0n = (nt % KT_PER_PASS) * 96;
            const uint32_t db = sb + OFF_FT + (uint32_t)(nt & 1) * FT_TILE;
            const int r = tid >> 2, cb = tid & 3;
#pragma unroll
            for (int j = 0; j < 3; j++) {
                const int c = cb + j * 4;
                cp16(db + r * FT_STRIDE + c * 16,
                     g_ftw_h + (size_t)(n0 + r) * KDIM + k0n + c * 8);
            }
        }
        CP_COMMIT();
        CP_WAIT(1);        // own tile-t copies retired (only t+1 pending)
        __syncthreads();   // everyone retired tile t -> visible CTA-wide

        const uint32_t ftile = sb + OFF_FT + (uint32_t)(t & 1) * FT_TILE;
        const int k0 = (t % KT_PER_PASS) * 96;
#pragma unroll
        for (int ks = 0; ks < 6; ks++) {
            const uint32_t ka = a_row + (uint32_t)(k0 + ks * 16) * 2 + OFF_AW;
            const char* pw = smc + (ka - sb);
            const char* pb = pw + (OFF_AB - OFF_AW);
            uint32_t aw0 = *(const uint32_t*)(pw);
            uint32_t aw1 = *(const uint32_t*)(pw + 8 * A_STRIDE_B);
            uint32_t aw2 = *(const uint32_t*)(pw + 16);
            uint32_t aw3 = *(const uint32_t*)(pw + 8 * A_STRIDE_B + 16);
            uint32_t ab0 = *(const uint32_t*)(pb);
            uint32_t ab1 = *(const uint32_t*)(pb + 8 * A_STRIDE_B);
            uint32_t ab2 = *(const uint32_t*)(pb + 16);
            uint32_t ab3 = *(const uint32_t*)(pb + 8 * A_STRIDE_B + 16);
#pragma unroll
            for (int b = 0; b < 4; b++) {
                const int n = warpN * 32 + b * 8 + (lane >> 2);
                const char* pf = smc + (ftile - sb) + n * FT_STRIDE +
                                 ks * 32 + (lane & 3) * 4;
                uint32_t b0 = *(const uint32_t*)(pf);
                uint32_t b1 = *(const uint32_t*)(pf + 16);
                mma_f16(wacc[b], aw0, aw1, aw2, aw3, b0, b1);
                mma_f16(bacc[b], ab0, ab1, ab2, ab3, b0, b1);
            }
        }
        __syncthreads();   // all done reading tile t -> its buffer reusable

        // ---- pass end: +ftb, stm mix, clip, l1 partial via mma ----
        if ((t % KT_PER_PASS) == KT_PER_PASS - 1) {
            const int chunk = t / KT_PER_PASS;
#pragma unroll
            for (int kg = 0; kg < 2; kg++) {
                uint32_t A1[4], A2[4];
#pragma unroll
                for (int h = 0; h < 2; h++) {
                    const int f = kg * 2 + h;
                    const int nidx = chunk * 64 + warpN * 32 + f * 8 + 2 * (lane & 3);
                    const float2 fb = __ldg(reinterpret_cast<const float2*>(ftb + nidx));
                    float a1v[4], a2v[4];
#pragma unroll
                    for (int j = 0; j < 4; j++) {
                        const float fbv = (j & 1) ? fb.y : fb.x;
                        const float sv = (j < 2) ? stm_lo : stm_hi;
                        const float wv = wacc[f][j] + fbv;
                        const float bv = bacc[f][j] + fbv;
                        a1v[j] = clip01(sv * wv + (1.0f - sv) * bv);
                        a2v[j] = clip01(sv * bv + (1.0f - sv) * wv);
                    }
                    A1[h * 2 + 0] = pack_h2(a1v[0], a1v[1]);
                    A1[h * 2 + 1] = pack_h2(a1v[2], a1v[3]);
                    A2[h * 2 + 0] = pack_h2(a2v[0], a2v[1]);
                    A2[h * 2 + 1] = pack_h2(a2v[2], a2v[3]);
                    wacc[f][0] = wacc[f][1] = wacc[f][2] = wacc[f][3] = 0.0f;
                    bacc[f][0] = bacc[f][1] = bacc[f][2] = bacc[f][3] = 0.0f;
                }
                const int kcol = chunk * 64 + warpN * 32 + kg * 16 + 2 * (lane & 3);
                const __half* bp = g_l1wh + (size_t)(lane >> 2) * (2 * HID) + kcol;
                uint32_t B10 = *reinterpret_cast<const uint32_t*>(bp);
                uint32_t B11 = *reinterpret_cast<const uint32_t*>(bp + 8);
                uint32_t B20 = *reinterpret_cast<const uint32_t*>(bp + HID);
                uint32_t B21 = *reinterpret_cast<const uint32_t*>(bp + HID + 8);
                mma_f16(sacc, A1[0], A1[1], A1[2], A1[3], B10, B11);
                mma_f16(sacc, A2[0], A2[1], A2[2], A2[3], B20, B21);
            }
        }
    }

    // ---- reduce l1 partials across 2 warpN groups, write to global ----
    __syncthreads();
    float* sred = reinterpret_cast<float*>(smc + OFF_FT);  // 2 x 64 x 8 floats
    {
        const int rlo = warpM * 16 + (lane >> 2);
        const int o0 = 2 * (lane & 3);
        float* g = sred + warpN * (TILEM * 8);
        g[rlo * 8 + o0] = sacc[0];
        g[rlo * 8 + o0 + 1] = sacc[1];
        g[(rlo + 8) * 8 + o0] = sacc[2];
        g[(rlo + 8) * 8 + o0 + 1] = sacc[3];
    }
    __syncthreads();

    if (tid < TILEM * 2) {   // 128 threads: (row, half) pairs write 4 floats each
        const int r = tid >> 1, half = tid & 1;
        float4 a = *reinterpret_cast<const float4*>(sred + r * 8 + half * 4);
        float4 b = *reinterpret_cast<const float4*>(sred + TILEM * 8 + r * 8 + half * 4);
        float4 s;
        s.x = a.x + b.x; s.y = a.y + b.y; s.z = a.z + b.z; s.w = a.w + b.w;
        *reinterpret_cast<float4*>(g_l1out + (size_t)(row0 + r) * 8 + half * 4) = s;
    }
}

// ---------------------------------------------------------------------------
// head: l1 sums -> l2 -> l3 -> sigmoid
// ---------------------------------------------------------------------------
__global__ __launch_bounds__(256) void nnue_head(
    const float* __restrict__ l1b, const float* __restrict__ l2w,
    const float* __restrict__ l2b, const float* __restrict__ l3w,
    const float* __restrict__ l3b, float* __restrict__ out, int B) {
    const int gr = blockIdx.x * 256 + threadIdx.x;
    const float4 s0 = *reinterpret_cast<const float4*>(g_l1out + (size_t)gr * 8);
    const float4 s1 = *reinterpret_cast<const float4*>(g_l1out + (size_t)gr * 8 + 4);
    float l2x[8];
    l2x[0] = clip01(s0.x + __ldg(&l1b[0]));
    l2x[1] = clip01(s0.y + __ldg(&l1b[1]));
    l2x[2] = clip01(s0.z + __ldg(&l1b[2]));
    l2x[3] = clip01(s0.w + __ldg(&l1b[3]));
    l2x[4] = clip01(s1.x + __ldg(&l1b[4]));
    l2x[5] = clip01(s1.y + __ldg(&l1b[5]));
    l2x[6] = clip01(s1.z + __ldg(&l1b[6]));
    l2x[7] = clip01(s1.w + __ldg(&l1b[7]));
    float rawv = __ldg(&l3b[0]);
#pragma unroll 1
    for (int j = 0; j < 32; j++) {
        float tacc = __ldg(&l2b[j]);
#pragma unroll
        for (int o = 0; o < 8; o++) tacc += __ldg(&l2w[j * 8 + o]) * l2x[o];
        rawv += __ldg(&l3w[j]) * clip01(tacc);
    }
    out[gr] = 1.0f / (1.0f + expf(-rawv));
    out[B + gr] = rawv;
}

// ---------------------------------------------------------------------------
// launch
// ---------------------------------------------------------------------------
extern "C" void kernel_launch(void* const* d_in, const int* in_sizes, int n_in,
                              void* d_out, int out_size) {
    const float* white = (const float*)d_in[0];
    const float* black = (const float*)d_in[1];
    const float* stm   = (const float*)d_in[2];
    const float* ftw   = (const float*)d_in[3];
    const float* ftb   = (const float*)d_in[4];
    const float* l1w   = (const float*)d_in[5];
    const float* l1b   = (const float*)d_in[6];
    const float* l2w   = (const float*)d_in[7];
    const float* l2b   = (const float*)d_in[8];
    const float* l3w   = (const float*)d_in[9];
    const float* l3b   = (const float*)d_in[10];
    float* out = (float*)d_out;

    const int B = in_sizes[2];

    nnue_prep<<<512, 256>>>(ftw, l1w);

    static int configured = 0;
    if (!configured) {
        cudaFuncSetAttribute(nnue_main, cudaFuncAttributeMaxDynamicSharedMemorySize,
                             SMEM_DYN);
        configured = 1;
    }
    nnue_main<<<B / TILEM, NTHREADS, SMEM_DYN>>>(white, black, stm, ftb);
    nnue_head<<<B / 256, 256>>>(l1b, l2w, l2b, l3w, l3b, out, B);
}